// round 6
// baseline (speedup 1.0000x reference)
#include <cuda_runtime.h>
#include <cstdint>

// ===========================================================================
// ChebyKANLinear, mma.sync m16n8k8 tf32. R5: 128x128 CTA tiles, 2 CTAs/SM
// (4 warps/SMSP) to cover gen-phase + barrier bubbles that left the tensor
// pipe at 51%. Fragment-packed B in gmem, fragment-layout A gen in smem.
// ===========================================================================

#define BATCH   8192
#define IN_F    1024
#define OUT_F   1024
#define BM      128
#define BN      128
#define KC      64            // 8 i-values * 8 degrees per chunk
#define NCHUNK  128           // IN_F / 8
#define A_BYTES 32768         // BM * KC * 4
#define B_BYTES 32768         // BN * KC * 4

// Static device scratch (no runtime allocation allowed)
__device__ float g_BF[(size_t)NCHUNK * 16 * 4096];  // B fragments, 32 MB
__device__ float g_Wt0[(size_t)IN_F * OUT_F];       // d=0 coefficients [i][o]
__device__ float g_T[(size_t)BATCH * IN_F];         // tanh(x)
__device__ float g_part[8 * OUT_F];
__device__ float g_bias[OUT_F];

// ---------------------------------------------------------------- utils
__device__ __forceinline__ uint32_t f2tf32(float f) {
    uint32_t u;
    asm("cvt.rna.tf32.f32 %0, %1;" : "=r"(u) : "f"(f));
    return u;
}
__device__ __forceinline__ float tf32r(float f) { return __uint_as_float(f2tf32(f)); }

__device__ __forceinline__ void cpa16(uint32_t dst, const void* src) {
    asm volatile("cp.async.cg.shared.global [%0], [%1], 16;\n" :: "r"(dst), "l"(src));
}
__device__ __forceinline__ void cpa_commit() { asm volatile("cp.async.commit_group;\n"); }
template <int N>
__device__ __forceinline__ void cpa_wait() {
    asm volatile("cp.async.wait_group %0;\n" :: "n"(N) : "memory");
}

__device__ __forceinline__ void lds128(uint4& v, uint32_t addr) {
    asm volatile("ld.shared.v4.b32 {%0,%1,%2,%3}, [%4];"
                 : "=r"(v.x), "=r"(v.y), "=r"(v.z), "=r"(v.w) : "r"(addr));
}
__device__ __forceinline__ void sts128(uint32_t addr, uint32_t a, uint32_t b,
                                       uint32_t c, uint32_t d) {
    asm volatile("st.shared.v4.b32 [%0], {%1,%2,%3,%4};"
                 :: "r"(addr), "r"(a), "r"(b), "r"(c), "r"(d));
}

__device__ __forceinline__ void mma8(float* c, const uint4& a, uint32_t b0, uint32_t b1) {
    asm volatile(
        "mma.sync.aligned.m16n8k8.row.col.f32.tf32.tf32.f32 "
        "{%0,%1,%2,%3},{%4,%5,%6,%7},{%8,%9},{%0,%1,%2,%3};\n"
        : "+f"(c[0]), "+f"(c[1]), "+f"(c[2]), "+f"(c[3])
        : "r"(a.x), "r"(a.y), "r"(a.z), "r"(a.w), "r"(b0), "r"(b1));
}

// A-fragment lane swizzle (conflict-free for gen STS.128 and consumer LDS.128)
__device__ __forceinline__ uint32_t a_lswz(uint32_t lane_c) {
    return (lane_c * 16u) ^ (((lane_c >> 3) & 3u) << 4);
}

// ---------------------------------------------------------------- prologues
// coef[i][o][d] -> g_BF in B-fragment order; g_Wt0[i][o] = coef[i][o][0].
// Per (c=i>>3, wnG=o>>6) block of 4096 floats:
//   word = (s*4 + nip)*128 + (g*4+t)*4 + parity*2 + reg
//   with s=i&7, nip=(o>>4)&3, parity=(o>>3)&1, g=o&7, t=(d-1)&3, reg=(d-1)>>2
__global__ void __launch_bounds__(256) prep_kernel(const float* __restrict__ coef) {
    __shared__ float frag[8192];   // per-i slice: [wnG16][nip4][lane32][4]
    const int i = blockIdx.x;
    const int c = i >> 3, s = i & 7;
    #pragma unroll
    for (int r = 0; r < 4; r++) {
        const int o = threadIdx.x + (r << 8);
        const float* cr = coef + (size_t)i * 9216 + (size_t)o * 9;
        float cv[9];
        #pragma unroll
        for (int d = 0; d < 9; d++) cv[d] = __ldg(cr + d);
        const int g = o & 7, par = (o >> 3) & 1, nip = (o >> 4) & 3, wnG = o >> 6;
        const int base = (wnG * 4 + nip) * 128 + par * 2;
        #pragma unroll
        for (int d = 1; d <= 8; d++) {
            const int tq = (d - 1) & 3, reg = (d - 1) >> 2;
            frag[base + (g * 4 + tq) * 4 + reg] = tf32r(cv[d]);
        }
        g_Wt0[(size_t)i * OUT_F + o] = cv[0];
    }
    __syncthreads();
    float4* dst = reinterpret_cast<float4*>(g_BF);
    const float4* src = reinterpret_cast<const float4*>(frag);
    #pragma unroll
    for (int k = 0; k < 8; k++) {
        const int fi4 = threadIdx.x + (k << 8);
        const int wnG = fi4 >> 7, rem = fi4 & 127;   // rem = nip*32 + lane
        dst[(size_t)(c * 16 + wnG) * 1024 + s * 128 + rem] = src[fi4];
    }
}

__global__ void __launch_bounds__(256) tanh_kernel(const float* __restrict__ X) {
    size_t q = ((size_t)blockIdx.x << 8) + threadIdx.x;   // float4 index
    float4 v = reinterpret_cast<const float4*>(X)[q];
    float4 o;
    { float e = __expf(2.f * v.x); o.x = 1.f - 2.f / (e + 1.f); }
    { float e = __expf(2.f * v.y); o.y = 1.f - 2.f / (e + 1.f); }
    { float e = __expf(2.f * v.z); o.z = 1.f - 2.f / (e + 1.f); }
    { float e = __expf(2.f * v.w); o.w = 1.f - 2.f / (e + 1.f); }
    reinterpret_cast<float4*>(g_T)[q] = o;
}

__global__ void __launch_bounds__(256) bias_part_kernel() {
    int o = (blockIdx.x << 8) + threadIdx.x;
    int i0 = blockIdx.y << 7;
    float s0 = 0.f, s1 = 0.f, s2 = 0.f, s3 = 0.f;
    #pragma unroll 8
    for (int i = 0; i < 128; i += 4) {
        s0 += g_Wt0[(size_t)(i0 + i + 0) * OUT_F + o];
        s1 += g_Wt0[(size_t)(i0 + i + 1) * OUT_F + o];
        s2 += g_Wt0[(size_t)(i0 + i + 2) * OUT_F + o];
        s3 += g_Wt0[(size_t)(i0 + i + 3) * OUT_F + o];
    }
    g_part[(blockIdx.y << 10) + o] = (s0 + s1) + (s2 + s3);
}
__global__ void __launch_bounds__(256) bias_red_kernel() {
    int o = (blockIdx.x << 8) + threadIdx.x;
    float s = 0.f;
    #pragma unroll
    for (int j = 0; j < 8; j++) s += g_part[(j << 10) + o];
    g_bias[o] = s;
}

// ---------------------------------------------------------------- main GEMM
// 256 threads = 8 warps (2 wm x 4 wn), warp tile 64x32 (4 mi x 4 ni).
// SMEM: A 32KB (single) + B 2x32KB (double) = 96KB -> 2 CTAs/SM.
__global__ void __launch_bounds__(256, 2) cheby_main(float* __restrict__ Out) {
    extern __shared__ uint8_t sm[];
    const uint32_t smA = (uint32_t)__cvta_generic_to_shared(sm);
    const uint32_t smB = smA + A_BYTES;

    const int tid  = threadIdx.x;
    const int lane = tid & 31;
    const int w    = tid >> 5;
    const int wm   = w >> 2;           // 0..1
    const int wn   = w & 3;            // 0..3
    const int g    = lane >> 2;
    const int t    = lane & 3;
    const int bm   = blockIdx.y << 7;
    const int bx   = blockIdx.x;
    const int bn   = bx << 7;

    float acc[4][4][4];
    #pragma unroll
    for (int mi = 0; mi < 4; mi++)
        #pragma unroll
        for (int ni = 0; ni < 4; ni++)
            #pragma unroll
            for (int q = 0; q < 4; q++) acc[mi][ni][q] = 0.f;

    // --- generator unit constants (2 units per thread; unchanged layout) ---
    int il[2];
    uint32_t genAddr[2][4];
    const float* rowLo[2];
    const float* rowHi[2];
    #pragma unroll
    for (int k = 0; k < 2; k++) {
        const int u = tid + (k << 8);
        il[k] = u >> 6;
        const int p = u & 63;
        const int wmU = p >> 5, miU = (p >> 3) & 3, gU = p & 7;
        const uint32_t blockBase = (uint32_t)(((il[k] * 2 + wmU) * 4 + miU) * 512);
        #pragma unroll
        for (int tq = 0; tq < 4; tq++)
            genAddr[k][tq] = smA + blockBase + a_lswz((uint32_t)(gU * 4 + tq));
        const int mU = (wmU << 6) + (miU << 4) + gU;
        rowLo[k] = g_T + (size_t)(bm + mU) * IN_F;
        rowHi[k] = rowLo[k] + (size_t)8 * IN_F;
    }

    // --- B cp.async source: 2 wnG groups (2048 float4) per chunk ---
    const float4* bsrc = reinterpret_cast<const float4*>(g_BF) + (size_t)bx * 2048;
    // per chunk c: src = bsrc + c*16384 + j,  j in [0,2048)

    // prefetch B(0)
    #pragma unroll
    for (int k = 0; k < 8; k++) {
        const int j = tid + (k << 8);
        cpa16(smB + (uint32_t)(j * 16), bsrc + j);
    }
    cpa_commit();

    // tanh values for chunk 0
    float tvc[4], tvn[4];
    #pragma unroll
    for (int k = 0; k < 2; k++) {
        tvc[2 * k]     = rowLo[k][il[k]];
        tvc[2 * k + 1] = rowHi[k][il[k]];
    }

    const uint32_t lsw = a_lswz((uint32_t)lane);
    const uint32_t aBaseW = smA + (uint32_t)(wm * 2048);
    // warp's B base: group = wn>>1 (64-col block, 16KB), half = wn&1 (nip pair)
    const uint32_t bBaseW = (uint32_t)((wn >> 1) * 16384 + (wn & 1) * 1024 + lane * 16);

    for (int c = 0; c < NCHUNK; c++) {
        const int stage = c & 1;

        // prefetch B(c+1) into the other buffer
        if (c + 1 < NCHUNK) {
            const float4* src = bsrc + (size_t)(c + 1) * 16384;
            const uint32_t dstB = smB + (uint32_t)((stage ^ 1) * B_BYTES);
            #pragma unroll
            for (int k = 0; k < 8; k++) {
                const int j = tid + (k << 8);
                cpa16(dstB + (uint32_t)(j * 16), src + j);
            }
            cpa_commit();
        }

        // --- generate A fragments for chunk c ---
        #pragma unroll
        for (int k = 0; k < 2; k++) {
            const float tl = tvc[2 * k], th = tvc[2 * k + 1];
            float Tl[8], Th[8];
            Tl[0] = tl; Th[0] = th;
            Tl[1] = 2.f * tl * tl - 1.f;
            Th[1] = 2.f * th * th - 1.f;
            #pragma unroll
            for (int d = 2; d < 8; d++) {
                Tl[d] = 2.f * tl * Tl[d - 1] - Tl[d - 2];
                Th[d] = 2.f * th * Th[d - 1] - Th[d - 2];
            }
            #pragma unroll
            for (int tq = 0; tq < 4; tq++)
                sts128(genAddr[k][tq], f2tf32(Tl[tq]), f2tf32(Th[tq]),
                       f2tf32(Tl[tq + 4]), f2tf32(Th[tq + 4]));
        }

        // prefetch tanh values for chunk c+1
        if (c + 1 < NCHUNK) {
            const int col = (c + 1) << 3;
            #pragma unroll
            for (int k = 0; k < 2; k++) {
                tvn[2 * k]     = rowLo[k][col + il[k]];
                tvn[2 * k + 1] = rowHi[k][col + il[k]];
            }
        }

        if (c + 1 < NCHUNK) cpa_wait<1>(); else cpa_wait<0>();
        __syncthreads();   // A written + B(stage) resident

        // --- MMA: 8 k8-steps x (4 mi x 4 ni) ---
        const uint32_t bBase = smB + (uint32_t)(stage * B_BYTES) + bBaseW;
        #pragma unroll
        for (int s = 0; s < 8; s++) {
            uint4 aC[4];
            #pragma unroll
            for (int mi = 0; mi < 4; mi++)
                lds128(aC[mi], aBaseW + (uint32_t)(s * 4096 + mi * 512) + lsw);
            uint4 bC[2];
            #pragma unroll
            for (int nip = 0; nip < 2; nip++)
                lds128(bC[nip], bBase + (uint32_t)(s * 2048 + nip * 512));
            #pragma unroll
            for (int ni = 0; ni < 4; ni++) {
                const uint32_t b0 = (ni & 1) ? bC[ni >> 1].z : bC[ni >> 1].x;
                const uint32_t b1 = (ni & 1) ? bC[ni >> 1].w : bC[ni >> 1].y;
                #pragma unroll
                for (int mi = 0; mi < 4; mi++)
                    mma8(acc[mi][ni], aC[mi], b0, b1);
            }
        }
        __syncthreads();   // A consumed before next gen overwrites it

        #pragma unroll
        for (int q = 0; q < 4; q++) tvc[q] = tvn[q];
    }

    // --- epilogue: add bias (d=0 term), store fp32 ---
    #pragma unroll
    for (int ni = 0; ni < 4; ni++) {
        const int cc = bn + (wn << 5) + (ni << 3) + (t << 1);
        const float2 bv = *reinterpret_cast<const float2*>(g_bias + cc);
        #pragma unroll
        for (int mi = 0; mi < 4; mi++) {
            const int r0 = bm + (wm << 6) + (mi << 4) + g;
            float2 o0 = { acc[mi][ni][0] + bv.x, acc[mi][ni][1] + bv.y };
            float2 o1 = { acc[mi][ni][2] + bv.x, acc[mi][ni][3] + bv.y };
            *reinterpret_cast<float2*>(Out + (size_t)r0 * OUT_F + cc)       = o0;
            *reinterpret_cast<float2*>(Out + (size_t)(r0 + 8) * OUT_F + cc) = o1;
        }
    }
}

// --------------------------------------------------------------------------
extern "C" void kernel_launch(void* const* d_in, const int* in_sizes, int n_in,
                              void* d_out, int out_size) {
    (void)in_sizes; (void)n_in; (void)out_size;
    const float* x    = (const float*)d_in[0];
    const float* coef = (const float*)d_in[1];
    float* out        = (float*)d_out;

    const int smem_bytes = A_BYTES + 2 * B_BYTES;   // 98304
    cudaFuncSetAttribute(cheby_main, cudaFuncAttributeMaxDynamicSharedMemorySize,
                         smem_bytes);

    prep_kernel<<<IN_F, 256>>>(coef);
    tanh_kernel<<<(BATCH * IN_F) / (256 * 4), 256>>>(x);
    bias_part_kernel<<<dim3(4, 8), 256>>>();
    bias_red_kernel<<<4, 256>>>();
    cheby_main<<<dim3(OUT_F / BN, BATCH / BM), 256, smem_bytes>>>(out);
}

// round 7
// speedup vs baseline: 1.0341x; 1.0341x over previous
#include <cuda_runtime.h>
#include <cstdint>

// ===========================================================================
// ChebyKANLinear, mma.sync m16n8k8 tf32.
// R6: 128x256 CTA tile (as R4) but 512 threads / 16 warps -> 4 warps/SMSP
// to saturate the legacy HMMA pipe (R2 model: 2 warps/SMSP => 51% active).
// Warp tile 32x64. Fragment-packed B in gmem, fragment-layout A gen in smem.
// ===========================================================================

#define BATCH   8192
#define IN_F    1024
#define OUT_F   1024
#define BM      128
#define BN      256
#define KC      64            // 8 i-values * 8 degrees per chunk
#define NCHUNK  128           // IN_F / 8
#define A_BYTES 32768         // BM * KC * 4
#define B_BYTES 65536         // BN * KC * 4
#define NTHR    512

// Static device scratch (no runtime allocation allowed)
__device__ float g_BF[(size_t)NCHUNK * 16 * 4096];  // B fragments, 32 MB
__device__ float g_Wt0[(size_t)IN_F * OUT_F];       // d=0 coefficients [i][o]
__device__ float g_T[(size_t)BATCH * IN_F];         // tanh(x)
__device__ float g_bias[OUT_F];

// ---------------------------------------------------------------- utils
__device__ __forceinline__ uint32_t f2tf32(float f) {
    uint32_t u;
    asm("cvt.rna.tf32.f32 %0, %1;" : "=r"(u) : "f"(f));
    return u;
}
__device__ __forceinline__ float tf32r(float f) { return __uint_as_float(f2tf32(f)); }

__device__ __forceinline__ void cpa16(uint32_t dst, const void* src) {
    asm volatile("cp.async.cg.shared.global [%0], [%1], 16;\n" :: "r"(dst), "l"(src));
}
__device__ __forceinline__ void cpa_commit() { asm volatile("cp.async.commit_group;\n"); }
template <int N>
__device__ __forceinline__ void cpa_wait() {
    asm volatile("cp.async.wait_group %0;\n" :: "n"(N) : "memory");
}

__device__ __forceinline__ void lds128(uint4& v, uint32_t addr) {
    asm volatile("ld.shared.v4.b32 {%0,%1,%2,%3}, [%4];"
                 : "=r"(v.x), "=r"(v.y), "=r"(v.z), "=r"(v.w) : "r"(addr));
}
__device__ __forceinline__ void sts128(uint32_t addr, uint32_t a, uint32_t b,
                                       uint32_t c, uint32_t d) {
    asm volatile("st.shared.v4.b32 [%0], {%1,%2,%3,%4};"
                 :: "r"(addr), "r"(a), "r"(b), "r"(c), "r"(d));
}

__device__ __forceinline__ void mma8(float* c, const uint4& a, uint32_t b0, uint32_t b1) {
    asm volatile(
        "mma.sync.aligned.m16n8k8.row.col.f32.tf32.tf32.f32 "
        "{%0,%1,%2,%3},{%4,%5,%6,%7},{%8,%9},{%0,%1,%2,%3};\n"
        : "+f"(c[0]), "+f"(c[1]), "+f"(c[2]), "+f"(c[3])
        : "r"(a.x), "r"(a.y), "r"(a.z), "r"(a.w), "r"(b0), "r"(b1));
}

// A-fragment lane swizzle (conflict-free for gen STS.128 and consumer LDS.128)
__device__ __forceinline__ uint32_t a_lswz(uint32_t lane_c) {
    return (lane_c * 16u) ^ (((lane_c >> 3) & 3u) << 4);
}

// ---------------------------------------------------------------- prologues
// coef[i][o][d] -> g_BF in B-fragment order; g_Wt0[i][o] = coef[i][o][0].
// Per (c=i>>3, wnG=o>>6) block of 4096 floats:
//   word = (s*4 + nip)*128 + (g*4+t)*4 + parity*2 + reg
//   with s=i&7, nip=(o>>4)&3, parity=(o>>3)&1, g=o&7, t=(d-1)&3, reg=(d-1)>>2
__global__ void __launch_bounds__(256) prep_kernel(const float* __restrict__ coef) {
    __shared__ float frag[8192];   // per-i slice: [wnG16][nip4][lane32][4]
    const int i = blockIdx.x;
    const int c = i >> 3, s = i & 7;
    #pragma unroll
    for (int r = 0; r < 4; r++) {
        const int o = threadIdx.x + (r << 8);
        const float* cr = coef + (size_t)i * 9216 + (size_t)o * 9;
        float cv[9];
        #pragma unroll
        for (int d = 0; d < 9; d++) cv[d] = __ldg(cr + d);
        const int g = o & 7, par = (o >> 3) & 1, nip = (o >> 4) & 3, wnG = o >> 6;
        const int base = (wnG * 4 + nip) * 128 + par * 2;
        #pragma unroll
        for (int d = 1; d <= 8; d++) {
            const int tq = (d - 1) & 3, reg = (d - 1) >> 2;
            frag[base + (g * 4 + tq) * 4 + reg] = tf32r(cv[d]);
        }
        g_Wt0[(size_t)i * OUT_F + o] = cv[0];
    }
    __syncthreads();
    float4* dst = reinterpret_cast<float4*>(g_BF);
    const float4* src = reinterpret_cast<const float4*>(frag);
    #pragma unroll
    for (int k = 0; k < 8; k++) {
        const int fi4 = threadIdx.x + (k << 8);
        const int wnG = fi4 >> 7, rem = fi4 & 127;   // rem = nip*32 + lane
        dst[(size_t)(c * 16 + wnG) * 1024 + s * 128 + rem] = src[fi4];
    }
}

// Fused: blocks [0,8192) compute tanh(x); blocks [8192,8196) compute bias.
__global__ void __launch_bounds__(256) tanh_bias_kernel(const float* __restrict__ X) {
    const int blk = blockIdx.x;
    if (blk < 8192) {
        size_t q = ((size_t)blk << 8) + threadIdx.x;   // float4 index
        float4 v = reinterpret_cast<const float4*>(X)[q];
        float4 o;
        { float e = __expf(2.f * v.x); o.x = 1.f - 2.f / (e + 1.f); }
        { float e = __expf(2.f * v.y); o.y = 1.f - 2.f / (e + 1.f); }
        { float e = __expf(2.f * v.z); o.z = 1.f - 2.f / (e + 1.f); }
        { float e = __expf(2.f * v.w); o.w = 1.f - 2.f / (e + 1.f); }
        reinterpret_cast<float4*>(g_T)[q] = o;
    } else {
        const int o = ((blk - 8192) << 8) + threadIdx.x;
        float s0 = 0.f, s1 = 0.f, s2 = 0.f, s3 = 0.f;
        #pragma unroll 4
        for (int i = 0; i < IN_F; i += 4) {
            s0 += g_Wt0[(size_t)(i + 0) * OUT_F + o];
            s1 += g_Wt0[(size_t)(i + 1) * OUT_F + o];
            s2 += g_Wt0[(size_t)(i + 2) * OUT_F + o];
            s3 += g_Wt0[(size_t)(i + 3) * OUT_F + o];
        }
        g_bias[o] = (s0 + s1) + (s2 + s3);
    }
}

// ---------------------------------------------------------------- main GEMM
// 512 threads = 16 warps (4 wm x 4 wn), warp tile 32x64 (2 mi x 8 ni).
// SMEM: A 32KB (single) + B 2x64KB (double) = 160KB, 1 CTA/SM, 4 warps/SMSP.
__global__ void __launch_bounds__(NTHR, 1) cheby_main(float* __restrict__ Out) {
    extern __shared__ uint8_t sm[];
    const uint32_t smA = (uint32_t)__cvta_generic_to_shared(sm);
    const uint32_t smB = smA + A_BYTES;

    const int tid  = threadIdx.x;
    const int lane = tid & 31;
    const int w    = tid >> 5;
    const int wm   = w >> 2;           // 0..3 (32-row block)
    const int wn   = w & 3;            // 0..3 (64-col block)
    const int g    = lane >> 2;
    const int t    = lane & 3;
    const int bm   = blockIdx.y << 7;
    const int bx   = blockIdx.x;
    const int bn   = bx << 8;

    float acc[2][8][4];
    #pragma unroll
    for (int mi = 0; mi < 2; mi++)
        #pragma unroll
        for (int ni = 0; ni < 8; ni++)
            #pragma unroll
            for (int q = 0; q < 4; q++) acc[mi][ni][q] = 0.f;

    // --- generator unit constants (1 unit per thread, 512 units) ---
    // u = tid: il = u>>6 (i within chunk), p = u&63 -> (wmU, miU, gU)
    const int il  = tid >> 6;
    const int p   = tid & 63;
    const int wmU = p >> 5, miU = (p >> 3) & 3, gU = p & 7;
    uint32_t genAddr[4];
    {
        const uint32_t blockBase = (uint32_t)(((il * 2 + wmU) * 4 + miU) * 512);
        #pragma unroll
        for (int tq = 0; tq < 4; tq++)
            genAddr[tq] = smA + blockBase + a_lswz((uint32_t)(gU * 4 + tq));
    }
    const int mU = (wmU << 6) + (miU << 4) + gU;
    const float* rowLo = g_T + (size_t)(bm + mU) * IN_F;
    const float* rowHi = rowLo + (size_t)8 * IN_F;

    // --- B cp.async source (contiguous per chunk): 4096 float4/chunk ---
    const float4* bsrc = reinterpret_cast<const float4*>(g_BF) + (size_t)bx * 4096;

    // prefetch B(0)
    #pragma unroll
    for (int k = 0; k < 8; k++) {
        const int j = tid + (k << 9);
        cpa16(smB + (uint32_t)(j * 16), bsrc + j);
    }
    cpa_commit();

    // tanh values for chunk 0
    float tvLo = rowLo[il], tvHi = rowHi[il];
    float tnLo, tnHi;

    const uint32_t lsw = a_lswz((uint32_t)lane);
    // A warp base: 32-row block -> wmU' = wm>>1 (2048B), miU pair = (wm&1)*2 (1024B)
    const uint32_t aBaseW = smA + (uint32_t)((wm >> 1) * 2048 + (wm & 1) * 1024);
    const uint32_t bBaseW = (uint32_t)(wn * 16384 + lane * 16);

    for (int c = 0; c < NCHUNK; c++) {
        const int stage = c & 1;

        // prefetch B(c+1) into the other buffer
        if (c + 1 < NCHUNK) {
            const float4* src = bsrc + (size_t)(c + 1) * 16384;
            const uint32_t dstB = smB + (uint32_t)((stage ^ 1) * B_BYTES);
            #pragma unroll
            for (int k = 0; k < 8; k++) {
                const int j = tid + (k << 9);
                cpa16(dstB + (uint32_t)(j * 16), src + j);
            }
            cpa_commit();
        }

        // --- generate A fragments for chunk c (1 unit: rows mU and mU+8) ---
        {
            const float tl = tvLo, th = tvHi;
            float Tl[8], Th[8];
            Tl[0] = tl; Th[0] = th;
            Tl[1] = 2.f * tl * tl - 1.f;
            Th[1] = 2.f * th * th - 1.f;
            #pragma unroll
            for (int d = 2; d < 8; d++) {
                Tl[d] = 2.f * tl * Tl[d - 1] - Tl[d - 2];
                Th[d] = 2.f * th * Th[d - 1] - Th[d - 2];
            }
            #pragma unroll
            for (int tq = 0; tq < 4; tq++)
                sts128(genAddr[tq], f2tf32(Tl[tq]), f2tf32(Th[tq]),
                       f2tf32(Tl[tq + 4]), f2tf32(Th[tq + 4]));
        }

        // prefetch tanh values for chunk c+1
        if (c + 1 < NCHUNK) {
            const int col = (c + 1) << 3;
            tnLo = rowLo[col + il];
            tnHi = rowHi[col + il];
        }

        if (c + 1 < NCHUNK) cpa_wait<1>(); else cpa_wait<0>();
        __syncthreads();   // A written + B(stage) resident

        // --- MMA: 8 k8-steps x (2 mi x 8 ni) ---
        const uint32_t bBase = smB + (uint32_t)(stage * B_BYTES) + bBaseW;
        #pragma unroll
        for (int s = 0; s < 8; s++) {
            uint4 aC[2];
            #pragma unroll
            for (int mi = 0; mi < 2; mi++)
                lds128(aC[mi], aBaseW + (uint32_t)(s * 4096 + mi * 512) + lsw);
            uint4 bC[4];
            #pragma unroll
            for (int nip = 0; nip < 4; nip++)
                lds128(bC[nip], bBase + (uint32_t)(s * 2048 + nip * 512));
            #pragma unroll
            for (int ni = 0; ni < 8; ni++) {
                const uint32_t b0 = (ni & 1) ? bC[ni >> 1].z : bC[ni >> 1].x;
                const uint32_t b1 = (ni & 1) ? bC[ni >> 1].w : bC[ni >> 1].y;
                #pragma unroll
                for (int mi = 0; mi < 2; mi++)
                    mma8(acc[mi][ni], aC[mi], b0, b1);
            }
        }
        __syncthreads();   // A consumed before next gen overwrites it

        tvLo = tnLo; tvHi = tnHi;
    }

    // --- epilogue: add bias (d=0 term), store fp32 ---
    #pragma unroll
    for (int ni = 0; ni < 8; ni++) {
        const int cc = bn + (wn << 6) + (ni << 3) + (t << 1);
        const float2 bv = *reinterpret_cast<const float2*>(g_bias + cc);
        #pragma unroll
        for (int mi = 0; mi < 2; mi++) {
            const int r0 = bm + (wm << 5) + (mi << 4) + g;
            float2 o0 = { acc[mi][ni][0] + bv.x, acc[mi][ni][1] + bv.y };
            float2 o1 = { acc[mi][ni][2] + bv.x, acc[mi][ni][3] + bv.y };
            *reinterpret_cast<float2*>(Out + (size_t)r0 * OUT_F + cc)       = o0;
            *reinterpret_cast<float2*>(Out + (size_t)(r0 + 8) * OUT_F + cc) = o1;
        }
    }
}

// --------------------------------------------------------------------------
extern "C" void kernel_launch(void* const* d_in, const int* in_sizes, int n_in,
                              void* d_out, int out_size) {
    (void)in_sizes; (void)n_in; (void)out_size;
    const float* x    = (const float*)d_in[0];
    const float* coef = (const float*)d_in[1];
    float* out        = (float*)d_out;

    const int smem_bytes = A_BYTES + 2 * B_BYTES;   // 163840
    cudaFuncSetAttribute(cheby_main, cudaFuncAttributeMaxDynamicSharedMemorySize,
                         smem_bytes);

    prep_kernel<<<IN_F, 256>>>(coef);
    tanh_bias_kernel<<<8196, 256>>>(x);
    cheby_main<<<dim3(OUT_F / BN, BATCH / BM), NTHR, smem_bytes>>>(out);
}

// round 8
// speedup vs baseline: 1.3720x; 1.3268x over previous
#include <cuda_runtime.h>
#include <cstdint>

// ===========================================================================
// ChebyKANLinear, mma.sync m16n8k8 tf32.
// R7: warp-specialized producer/consumer. Warps 0-7 (256 thr): pure MMA on
// 128x256 tile (R4 layout, saturates pipe). Warps 8-11 (128 thr): generate
// A(c+1) + cp.async B(c+1) + tanh loads, overlapped with chunk-c MMAs.
// Double-buffered A and B, ONE barrier per chunk.
// ===========================================================================

#define BATCH   8192
#define IN_F    1024
#define OUT_F   1024
#define BM      128
#define BN      256
#define KC      64            // 8 i-values * 8 degrees per chunk
#define NCHUNK  128           // IN_F / 8
#define A_BYTES 32768         // BM * KC * 4
#define B_BYTES 65536         // BN * KC * 4
#define NTHR    384

// Static device scratch (no runtime allocation allowed)
__device__ float g_BF[(size_t)NCHUNK * 16 * 4096];  // B fragments, 32 MB
__device__ float g_Wt0[(size_t)IN_F * OUT_F];       // d=0 coefficients [i][o]
__device__ float g_T[(size_t)BATCH * IN_F];         // tanh(x)
__device__ float g_bias[OUT_F];

// ---------------------------------------------------------------- utils
__device__ __forceinline__ uint32_t f2tf32(float f) {
    uint32_t u;
    asm("cvt.rna.tf32.f32 %0, %1;" : "=r"(u) : "f"(f));
    return u;
}
__device__ __forceinline__ float tf32r(float f) { return __uint_as_float(f2tf32(f)); }

__device__ __forceinline__ void cpa16(uint32_t dst, const void* src) {
    asm volatile("cp.async.cg.shared.global [%0], [%1], 16;\n" :: "r"(dst), "l"(src));
}
__device__ __forceinline__ void cpa_commit() { asm volatile("cp.async.commit_group;\n"); }
__device__ __forceinline__ void cpa_wait0() {
    asm volatile("cp.async.wait_group 0;\n" ::: "memory");
}

__device__ __forceinline__ void lds128(uint4& v, uint32_t addr) {
    asm volatile("ld.shared.v4.b32 {%0,%1,%2,%3}, [%4];"
                 : "=r"(v.x), "=r"(v.y), "=r"(v.z), "=r"(v.w) : "r"(addr));
}
__device__ __forceinline__ void sts128(uint32_t addr, uint32_t a, uint32_t b,
                                       uint32_t c, uint32_t d) {
    asm volatile("st.shared.v4.b32 [%0], {%1,%2,%3,%4};"
                 :: "r"(addr), "r"(a), "r"(b), "r"(c), "r"(d));
}

__device__ __forceinline__ void mma8(float* c, const uint4& a, uint32_t b0, uint32_t b1) {
    asm volatile(
        "mma.sync.aligned.m16n8k8.row.col.f32.tf32.tf32.f32 "
        "{%0,%1,%2,%3},{%4,%5,%6,%7},{%8,%9},{%0,%1,%2,%3};\n"
        : "+f"(c[0]), "+f"(c[1]), "+f"(c[2]), "+f"(c[3])
        : "r"(a.x), "r"(a.y), "r"(a.z), "r"(a.w), "r"(b0), "r"(b1));
}

// A-fragment lane swizzle (conflict-free for gen STS.128 and consumer LDS.128)
__device__ __forceinline__ uint32_t a_lswz(uint32_t lane_c) {
    return (lane_c * 16u) ^ (((lane_c >> 3) & 3u) << 4);
}

// ---------------------------------------------------------------- prologues
// coef[i][o][d] -> g_BF in B-fragment order; g_Wt0[i][o] = coef[i][o][0].
__global__ void __launch_bounds__(256) prep_kernel(const float* __restrict__ coef) {
    __shared__ float frag[8192];   // per-i slice: [wnG16][nip4][lane32][4]
    const int i = blockIdx.x;
    const int c = i >> 3, s = i & 7;
    #pragma unroll
    for (int r = 0; r < 4; r++) {
        const int o = threadIdx.x + (r << 8);
        const float* cr = coef + (size_t)i * 9216 + (size_t)o * 9;
        float cv[9];
        #pragma unroll
        for (int d = 0; d < 9; d++) cv[d] = __ldg(cr + d);
        const int g = o & 7, par = (o >> 3) & 1, nip = (o >> 4) & 3, wnG = o >> 6;
        const int base = (wnG * 4 + nip) * 128 + par * 2;
        #pragma unroll
        for (int d = 1; d <= 8; d++) {
            const int tq = (d - 1) & 3, reg = (d - 1) >> 2;
            frag[base + (g * 4 + tq) * 4 + reg] = tf32r(cv[d]);
        }
        g_Wt0[(size_t)i * OUT_F + o] = cv[0];
    }
    __syncthreads();
    float4* dst = reinterpret_cast<float4*>(g_BF);
    const float4* src = reinterpret_cast<const float4*>(frag);
    #pragma unroll
    for (int k = 0; k < 8; k++) {
        const int fi4 = threadIdx.x + (k << 8);
        const int wnG = fi4 >> 7, rem = fi4 & 127;   // rem = nip*32 + lane
        dst[(size_t)(c * 16 + wnG) * 1024 + s * 128 + rem] = src[fi4];
    }
}

// Fused: blocks [0,8192) compute tanh(x); blocks [8192,8196) compute bias.
__global__ void __launch_bounds__(256) tanh_bias_kernel(const float* __restrict__ X) {
    const int blk = blockIdx.x;
    if (blk < 8192) {
        size_t q = ((size_t)blk << 8) + threadIdx.x;   // float4 index
        float4 v = reinterpret_cast<const float4*>(X)[q];
        float4 o;
        { float e = __expf(2.f * v.x); o.x = 1.f - 2.f / (e + 1.f); }
        { float e = __expf(2.f * v.y); o.y = 1.f - 2.f / (e + 1.f); }
        { float e = __expf(2.f * v.z); o.z = 1.f - 2.f / (e + 1.f); }
        { float e = __expf(2.f * v.w); o.w = 1.f - 2.f / (e + 1.f); }
        reinterpret_cast<float4*>(g_T)[q] = o;
    } else {
        const int o = ((blk - 8192) << 8) + threadIdx.x;
        float s0 = 0.f, s1 = 0.f, s2 = 0.f, s3 = 0.f;
        #pragma unroll 4
        for (int i = 0; i < IN_F; i += 4) {
            s0 += g_Wt0[(size_t)(i + 0) * OUT_F + o];
            s1 += g_Wt0[(size_t)(i + 1) * OUT_F + o];
            s2 += g_Wt0[(size_t)(i + 2) * OUT_F + o];
            s3 += g_Wt0[(size_t)(i + 3) * OUT_F + o];
        }
        g_bias[o] = (s0 + s1) + (s2 + s3);
    }
}

// ---------------------------------------------------------------- main GEMM
// SMEM: A 2x32KB + B 2x64KB = 192KB. One CTA/SM.
__global__ void __launch_bounds__(NTHR, 1) cheby_main(float* __restrict__ Out) {
    extern __shared__ uint8_t sm[];
    const uint32_t smA = (uint32_t)__cvta_generic_to_shared(sm);
    const uint32_t smB = smA + 2 * A_BYTES;

    const int tid  = threadIdx.x;
    const int lane = tid & 31;
    const int w    = tid >> 5;
    const int bm   = blockIdx.y << 7;
    const int bx   = blockIdx.x;
    const int bn   = bx << 8;

    const float4* bsrc = reinterpret_cast<const float4*>(g_BF) + (size_t)bx * 4096;

    if (w < 8) {
        // ======================= CONSUMER (256 threads) =====================
        const int wm = w >> 2;           // 0..1
        const int wn = w & 3;            // 0..3
        const int g  = lane >> 2;
        const int t  = lane & 3;
        const uint32_t lsw = a_lswz((uint32_t)lane);

        float acc[4][8][4];
        #pragma unroll
        for (int mi = 0; mi < 4; mi++)
            #pragma unroll
            for (int ni = 0; ni < 8; ni++)
                #pragma unroll
                for (int q = 0; q < 4; q++) acc[mi][ni][q] = 0.f;

        __syncthreads();    // chunk 0 ready

        for (int c = 0; c < NCHUNK; c++) {
            const int stage = c & 1;
            const uint32_t aBase = smA + (uint32_t)(stage * A_BYTES + wm * 2048);
            const uint32_t bBase = smB + (uint32_t)(stage * B_BYTES + wn * 16384 + lane * 16);

            #pragma unroll
            for (int s = 0; s < 8; s++) {
                uint4 aC[4];
                #pragma unroll
                for (int mi = 0; mi < 4; mi++)
                    lds128(aC[mi], aBase + (uint32_t)(s * 4096 + mi * 512) + lsw);
                uint4 bC[4];
                #pragma unroll
                for (int nip = 0; nip < 4; nip++)
                    lds128(bC[nip], bBase + (uint32_t)(s * 2048 + nip * 512));
                #pragma unroll
                for (int ni = 0; ni < 8; ni++) {
                    const uint32_t b0 = (ni & 1) ? bC[ni >> 1].z : bC[ni >> 1].x;
                    const uint32_t b1 = (ni & 1) ? bC[ni >> 1].w : bC[ni >> 1].y;
                    #pragma unroll
                    for (int mi = 0; mi < 4; mi++)
                        mma8(acc[mi][ni], aC[mi], b0, b1);
                }
            }
            __syncthreads();    // chunk c consumed / chunk c+1 produced
        }

        // --- epilogue: add bias (d=0 term), store fp32 ---
        #pragma unroll
        for (int ni = 0; ni < 8; ni++) {
            const int cc = bn + (wn << 6) + (ni << 3) + (t << 1);
            const float2 bv = *reinterpret_cast<const float2*>(g_bias + cc);
            #pragma unroll
            for (int mi = 0; mi < 4; mi++) {
                const int r0 = bm + (wm << 6) + (mi << 4) + g;
                float2 o0 = { acc[mi][ni][0] + bv.x, acc[mi][ni][1] + bv.y };
                float2 o1 = { acc[mi][ni][2] + bv.x, acc[mi][ni][3] + bv.y };
                *reinterpret_cast<float2*>(Out + (size_t)r0 * OUT_F + cc)       = o0;
                *reinterpret_cast<float2*>(Out + (size_t)(r0 + 8) * OUT_F + cc) = o1;
            }
        }
    } else {
        // ======================= PRODUCER (128 threads) =====================
        const int ptid = tid - 256;
        const int il0  = ptid >> 6;            // 0 or 1
        const int p    = ptid & 63;
        const int wmU = p >> 5, miU = (p >> 3) & 3, gU = p & 7;
        uint32_t lswz4[4];
        #pragma unroll
        for (int tq = 0; tq < 4; tq++)
            lswz4[tq] = a_lswz((uint32_t)(gU * 4 + tq));
        const int mU = (wmU << 6) + (miU << 4) + gU;
        const float* rowLo = g_T + (size_t)(bm + mU) * IN_F;
        const float* rowHi = rowLo + (size_t)8 * IN_F;

        // produce(n): tanh loads -> B cp.async -> A gen -> wait
        #define PRODUCE(n)                                                        \
        do {                                                                      \
            const int nb_ = (n) & 1;                                              \
            const int cb_ = (n) << 3;                                             \
            float tv_[8];                                                         \
            _Pragma("unroll")                                                     \
            for (int k = 0; k < 4; k++) {                                         \
                const int ii = cb_ + il0 + (k << 1);                              \
                tv_[2 * k]     = rowLo[ii];                                       \
                tv_[2 * k + 1] = rowHi[ii];                                       \
            }                                                                     \
            const float4* src_ = bsrc + (size_t)(n) * 16384;                      \
            const uint32_t dstB_ = smB + (uint32_t)(nb_ * B_BYTES);               \
            _Pragma("unroll")                                                     \
            for (int k = 0; k < 32; k++) {                                        \
                const int j = ptid + (k << 7);                                    \
                cpa16(dstB_ + (uint32_t)(j * 16), src_ + j);                      \
            }                                                                     \
            cpa_commit();                                                         \
            const uint32_t aDst_ = smA + (uint32_t)(nb_ * A_BYTES);               \
            _Pragma("unroll")                                                     \
            for (int k = 0; k < 4; k++) {                                         \
                const int il = il0 + (k << 1);                                    \
                const uint32_t bb_ =                                              \
                    aDst_ + (uint32_t)((((il * 2 + wmU) * 4 + miU)) * 512);       \
                const float tl = tv_[2 * k], th = tv_[2 * k + 1];                 \
                float Tl[8], Th[8];                                               \
                Tl[0] = tl; Th[0] = th;                                           \
                Tl[1] = 2.f * tl * tl - 1.f;                                      \
                Th[1] = 2.f * th * th - 1.f;                                      \
                _Pragma("unroll")                                                 \
                for (int d = 2; d < 8; d++) {                                     \
                    Tl[d] = 2.f * tl * Tl[d - 1] - Tl[d - 2];                     \
                    Th[d] = 2.f * th * Th[d - 1] - Th[d - 2];                     \
                }                                                                 \
                _Pragma("unroll")                                                 \
                for (int tq = 0; tq < 4; tq++)                                    \
                    sts128(bb_ + lswz4[tq], f2tf32(Tl[tq]), f2tf32(Th[tq]),       \
                           f2tf32(Tl[tq + 4]), f2tf32(Th[tq + 4]));               \
            }                                                                     \
            cpa_wait0();                                                          \
        } while (0)

        PRODUCE(0);
        __syncthreads();    // chunk 0 ready

        for (int c = 0; c < NCHUNK; c++) {
            if (c + 1 < NCHUNK) PRODUCE(c + 1);
            __syncthreads();
        }
        #undef PRODUCE
    }
}

// --------------------------------------------------------------------------
extern "C" void kernel_launch(void* const* d_in, const int* in_sizes, int n_in,
                              void* d_out, int out_size) {
    (void)in_sizes; (void)n_in; (void)out_size;
    const float* x    = (const float*)d_in[0];
    const float* coef = (const float*)d_in[1];
    float* out        = (float*)d_out;

    const int smem_bytes = 2 * A_BYTES + 2 * B_BYTES;   // 196608
    cudaFuncSetAttribute(cheby_main, cudaFuncAttributeMaxDynamicSharedMemorySize,
                         smem_bytes);

    prep_kernel<<<IN_F, 256>>>(coef);
    tanh_bias_kernel<<<8196, 256>>>(x);
    cheby_main<<<dim3(OUT_F / BN, BATCH / BM), NTHR, smem_bytes>>>(out);
}

// round 9
// speedup vs baseline: 2.2975x; 1.6745x over previous
#include <cuda_runtime.h>
#include <cuda_fp16.h>
#include <cstdint>

// ===========================================================================
// ChebyKANLinear, mma.sync m16n8k16 FP16 (fp32 accumulate).
// Numerics: fp16 mantissa == tf32 mantissa (11 bits). A = T_d(tanh x) in
// [-1,1]; B = coef * 2^12 (exact scale -> all fp16-normal); epilogue
// multiplies by 2^-12. Error identical to the tf32 path (~2.4e-4).
// R8: halves MMA count + smem traffic vs R7; 3-stage ring, producer runs
// 2 chunks ahead (cp.async wait_group 1) so it never blocks the barrier.
// ===========================================================================

#define BATCH   8192
#define IN_F    1024
#define OUT_F   1024
#define BM      128
#define BN      256
#define KC      64            // 8 i-values * 8 degrees per chunk
#define NCHUNK  128           // IN_F / 8
#define A_BYTES 16384         // BM * KC * 2 (fp16)
#define B_BYTES 32768         // BN * KC * 2 (fp16)
#define STAGE_BYTES (A_BYTES + B_BYTES)
#define NSTG    3
#define NTHR    384
#define CSCALE  4096.0f
#define OSCALE  (1.0f / 4096.0f)

// Static device scratch (no runtime allocation allowed)
__device__ uint32_t g_BF[(size_t)NCHUNK * 16 * 2048];  // B fp16 frags, 16 MB
__device__ float g_Wt0[(size_t)IN_F * OUT_F];          // d=0 coefficients [i][o]
__device__ float g_T[(size_t)BATCH * IN_F];            // tanh(x)
__device__ float g_bias[OUT_F];

// ---------------------------------------------------------------- utils
__device__ __forceinline__ uint32_t h2pack(float lo, float hi) {
    __half2 h = __floats2half2_rn(lo, hi);
    return *reinterpret_cast<uint32_t*>(&h);
}

__device__ __forceinline__ void cpa16(uint32_t dst, const void* src) {
    asm volatile("cp.async.cg.shared.global [%0], [%1], 16;\n" :: "r"(dst), "l"(src));
}
__device__ __forceinline__ void cpa_commit() { asm volatile("cp.async.commit_group;\n"); }
template <int N>
__device__ __forceinline__ void cpa_wait() {
    asm volatile("cp.async.wait_group %0;\n" :: "n"(N) : "memory");
}

__device__ __forceinline__ void lds128(uint4& v, uint32_t addr) {
    asm volatile("ld.shared.v4.b32 {%0,%1,%2,%3}, [%4];"
                 : "=r"(v.x), "=r"(v.y), "=r"(v.z), "=r"(v.w) : "r"(addr));
}
__device__ __forceinline__ void sts128(uint32_t addr, uint32_t a, uint32_t b,
                                       uint32_t c, uint32_t d) {
    asm volatile("st.shared.v4.b32 [%0], {%1,%2,%3,%4};"
                 :: "r"(addr), "r"(a), "r"(b), "r"(c), "r"(d));
}

__device__ __forceinline__ void mma16(float* c, const uint4& a, uint32_t b0, uint32_t b1) {
    asm volatile(
        "mma.sync.aligned.m16n8k16.row.col.f32.f16.f16.f32 "
        "{%0,%1,%2,%3},{%4,%5,%6,%7},{%8,%9},{%0,%1,%2,%3};\n"
        : "+f"(c[0]), "+f"(c[1]), "+f"(c[2]), "+f"(c[3])
        : "r"(a.x), "r"(a.y), "r"(a.z), "r"(a.w), "r"(b0), "r"(b1));
}

// A-fragment lane swizzle (conflict-free for gen STS.128 and consumer LDS.128)
__device__ __forceinline__ uint32_t a_lswz(uint32_t lane_c) {
    return (lane_c * 16u) ^ (((lane_c >> 3) & 3u) << 4);
}

// ---------------------------------------------------------------- prologues
// B fragments (fp16, scaled by 2^12). Block b handles i-pair (i0, i0+1),
// i0 = (b>>2)*8 + (b&3)*2, i.e. chunk c=b>>2, step s=b&3.
// 16B unit at (c, wnG, s, nip, lane=(g,t)): words =
//   [col_even,i0][col_even,i1][col_odd,i0][col_odd,i1], each h2(d=2t+1, 2t+2)
__global__ void __launch_bounds__(256) prep_kernel(const float* __restrict__ coef) {
    __shared__ uint32_t stg[8192];     // [wnG16][nip4][lane32][w4]
    const int b = blockIdx.x;
    const int c = b >> 2, s = b & 3;
    const int i0 = c * 8 + s * 2;
    #pragma unroll
    for (int r = 0; r < 4; r++) {
        const int col = threadIdx.x + (r << 8);
        const float* c0 = coef + (size_t)i0 * 9216 + (size_t)col * 9;
        const float* c1 = c0 + 9216;
        float cv0[9], cv1[9];
        #pragma unroll
        for (int d = 0; d < 9; d++) { cv0[d] = __ldg(c0 + d); cv1[d] = __ldg(c1 + d); }
        const int g = col & 7, colpar = (col >> 3) & 1;
        const int nip = (col >> 4) & 3, wnG = col >> 6;
        const int base = wnG * 512 + nip * 128 + colpar * 2;
        #pragma unroll
        for (int t = 0; t < 4; t++) {
            stg[base + (g * 4 + t) * 4 + 0] =
                h2pack(cv0[2 * t + 1] * CSCALE, cv0[2 * t + 2] * CSCALE);
            stg[base + (g * 4 + t) * 4 + 1] =
                h2pack(cv1[2 * t + 1] * CSCALE, cv1[2 * t + 2] * CSCALE);
        }
        g_Wt0[(size_t)i0 * OUT_F + col]       = cv0[0];
        g_Wt0[(size_t)(i0 + 1) * OUT_F + col] = cv1[0];
    }
    __syncthreads();
    // write s-slice: per (c,wnG) block of 512 float4, slice at s*128
    float4* dst = reinterpret_cast<float4*>(g_BF);
    const float4* src = reinterpret_cast<const float4*>(stg);
    #pragma unroll
    for (int k = 0; k < 8; k++) {
        const int q = threadIdx.x + (k << 8);   // 0..2047
        const int wnG = q >> 7, inner = q & 127;
        dst[(size_t)(c * 16 + wnG) * 512 + s * 128 + inner] = src[q];
    }
}

// Fused: blocks [0,8192) compute tanh(x); blocks [8192,8196) compute bias.
__global__ void __launch_bounds__(256) tanh_bias_kernel(const float* __restrict__ X) {
    const int blk = blockIdx.x;
    if (blk < 8192) {
        size_t q = ((size_t)blk << 8) + threadIdx.x;   // float4 index
        float4 v = reinterpret_cast<const float4*>(X)[q];
        float4 o;
        { float e = __expf(2.f * v.x); o.x = 1.f - 2.f / (e + 1.f); }
        { float e = __expf(2.f * v.y); o.y = 1.f - 2.f / (e + 1.f); }
        { float e = __expf(2.f * v.z); o.z = 1.f - 2.f / (e + 1.f); }
        { float e = __expf(2.f * v.w); o.w = 1.f - 2.f / (e + 1.f); }
        reinterpret_cast<float4*>(g_T)[q] = o;
    } else {
        const int o = ((blk - 8192) << 8) + threadIdx.x;
        float s0 = 0.f, s1 = 0.f, s2 = 0.f, s3 = 0.f;
        #pragma unroll 4
        for (int i = 0; i < IN_F; i += 4) {
            s0 += g_Wt0[(size_t)(i + 0) * OUT_F + o];
            s1 += g_Wt0[(size_t)(i + 1) * OUT_F + o];
            s2 += g_Wt0[(size_t)(i + 2) * OUT_F + o];
            s3 += g_Wt0[(size_t)(i + 3) * OUT_F + o];
        }
        g_bias[o] = (s0 + s1) + (s2 + s3);
    }
}

// ---------------------------------------------------------------- main GEMM
// 384 thr: warps 0-7 consumers (128x256 tile, warp 64x64, m16n8k16),
// warps 8-11 producers. 3-stage ring (A 16KB + B 32KB per stage) = 144KB.
__global__ void __launch_bounds__(NTHR, 1) cheby_main(float* __restrict__ Out) {
    extern __shared__ uint8_t sm[];
    const uint32_t smA = (uint32_t)__cvta_generic_to_shared(sm);          // 3 x 16KB
    const uint32_t smB = smA + NSTG * A_BYTES;                            // 3 x 32KB

    const int tid  = threadIdx.x;
    const int lane = tid & 31;
    const int w    = tid >> 5;
    const int bm   = blockIdx.y << 7;
    const int bx   = blockIdx.x;
    const int bn   = bx << 8;

    const float4* bsrc = reinterpret_cast<const float4*>(g_BF);

    if (w < 8) {
        // ======================= CONSUMER (256 threads) =====================
        const int wm = w >> 2;           // 0..1 (64-row block)
        const int wn = w & 3;            // 0..3 (64-col block)
        const int g  = lane >> 2;
        const int t  = lane & 3;
        const uint32_t lsw = a_lswz((uint32_t)lane);

        float acc[4][8][4];
        #pragma unroll
        for (int mi = 0; mi < 4; mi++)
            #pragma unroll
            for (int ni = 0; ni < 8; ni++)
                #pragma unroll
                for (int q = 0; q < 4; q++) acc[mi][ni][q] = 0.f;

        __syncthreads();    // chunks 0,1 produced; B0 complete

        for (int c = 0; c < NCHUNK; c++) {
            const int st = c % NSTG;
            // A: [s:4][G:8][512B]; warp rows: G = wm*4+mi
            const uint32_t aBase = smA + (uint32_t)(st * A_BYTES + wm * 2048) + lsw;
            // B: [wnG:4][s:4][nip:4][lane*16]
            const uint32_t bBase = smB + (uint32_t)(st * B_BYTES + wn * 8192 + lane * 16);

            #pragma unroll
            for (int s = 0; s < 4; s++) {
                uint4 aC[4];
                #pragma unroll
                for (int mi = 0; mi < 4; mi++)
                    lds128(aC[mi], aBase + (uint32_t)(s * 4096 + mi * 512));
                uint4 bC[4];
                #pragma unroll
                for (int nip = 0; nip < 4; nip++)
                    lds128(bC[nip], bBase + (uint32_t)(s * 2048 + nip * 512));
                #pragma unroll
                for (int ni = 0; ni < 8; ni++) {
                    const uint32_t b0 = (ni & 1) ? bC[ni >> 1].z : bC[ni >> 1].x;
                    const uint32_t b1 = (ni & 1) ? bC[ni >> 1].w : bC[ni >> 1].y;
                    #pragma unroll
                    for (int mi = 0; mi < 4; mi++)
                        mma16(acc[mi][ni], aC[mi], b0, b1);
                }
            }
            __syncthreads();
        }

        // --- epilogue: out = acc * 2^-12 + bias ---
        #pragma unroll
        for (int ni = 0; ni < 8; ni++) {
            const int cc = bn + (wn << 6) + (ni << 3) + (t << 1);
            const float2 bv = *reinterpret_cast<const float2*>(g_bias + cc);
            #pragma unroll
            for (int mi = 0; mi < 4; mi++) {
                const int r0 = bm + (wm << 6) + (mi << 4) + g;
                float2 o0 = { fmaf(acc[mi][ni][0], OSCALE, bv.x),
                              fmaf(acc[mi][ni][1], OSCALE, bv.y) };
                float2 o1 = { fmaf(acc[mi][ni][2], OSCALE, bv.x),
                              fmaf(acc[mi][ni][3], OSCALE, bv.y) };
                *reinterpret_cast<float2*>(Out + (size_t)r0 * OUT_F + cc)       = o0;
                *reinterpret_cast<float2*>(Out + (size_t)(r0 + 8) * OUT_F + cc) = o1;
            }
        }
    } else {
        // ======================= PRODUCER (128 threads) =====================
        const int ptid = tid - 256;
        // 2 generator units per thread: u = ptid, ptid+128
        // unit u: s = u&3, g = (u>>2)&7, G = u>>5; rows G*16+g, +8; i = 8c+2s,+1

        #define PRODUCE(n)                                                        \
        do {                                                                      \
            const int st_ = (n) % NSTG;                                           \
            /* B: 4 wnG blocks of 512 float4 */                                   \
            const uint32_t dstB_ = smB + (uint32_t)(st_ * B_BYTES);               \
            _Pragma("unroll")                                                     \
            for (int k = 0; k < 16; k++) {                                        \
                const int wng = k >> 2;                                           \
                const int inner = ptid + ((k & 3) << 7);                          \
                cpa16(dstB_ + (uint32_t)(wng * 8192 + inner * 16),                \
                      bsrc + (size_t)((n) * 16 + (bx << 2) + wng) * 512 + inner); \
            }                                                                     \
            cpa_commit();                                                         \
            /* A generation */                                                    \
            const uint32_t aDst_ = smA + (uint32_t)(st_ * A_BYTES);               \
            _Pragma("unroll")                                                     \
            for (int e = 0; e < 2; e++) {                                         \
                const int u = ptid + (e << 7);                                    \
                const int s_ = u & 3, g_ = (u >> 2) & 7, G_ = u >> 5;             \
                const int rA = bm + (G_ << 4) + g_;                               \
                const float2 tA = *reinterpret_cast<const float2*>(               \
                    g_T + (size_t)rA * IN_F + ((n) << 3) + (s_ << 1));            \
                const float2 tB = *reinterpret_cast<const float2*>(               \
                    g_T + (size_t)(rA + 8) * IN_F + ((n) << 3) + (s_ << 1));      \
                float TA0[8], TA1[8], TB0[8], TB1[8];                             \
                TA0[0] = tA.x; TA1[0] = tA.y; TB0[0] = tB.x; TB1[0] = tB.y;       \
                TA0[1] = 2.f * tA.x * tA.x - 1.f;                                 \
                TA1[1] = 2.f * tA.y * tA.y - 1.f;                                 \
                TB0[1] = 2.f * tB.x * tB.x - 1.f;                                 \
                TB1[1] = 2.f * tB.y * tB.y - 1.f;                                 \
                _Pragma("unroll")                                                 \
                for (int d = 2; d < 8; d++) {                                     \
                    TA0[d] = 2.f * tA.x * TA0[d - 1] - TA0[d - 2];                \
                    TA1[d] = 2.f * tA.y * TA1[d - 1] - TA1[d - 2];                \
                    TB0[d] = 2.f * tB.x * TB0[d - 1] - TB0[d - 2];                \
                    TB1[d] = 2.f * tB.y * TB1[d - 1] - TB1[d - 2];                \
                }                                                                 \
                const uint32_t ab_ = aDst_ + (uint32_t)(s_ * 4096 + G_ * 512);    \
                _Pragma("unroll")                                                 \
                for (int t = 0; t < 4; t++)                                       \
                    sts128(ab_ + a_lswz((uint32_t)(g_ * 4 + t)),                  \
                           h2pack(TA0[2 * t], TA0[2 * t + 1]),                    \
                           h2pack(TB0[2 * t], TB0[2 * t + 1]),                    \
                           h2pack(TA1[2 * t], TA1[2 * t + 1]),                    \
                           h2pack(TB1[2 * t], TB1[2 * t + 1]));                   \
            }                                                                     \
        } while (0)

        PRODUCE(0);
        PRODUCE(1);
        cpa_wait<1>();       // B(0) complete
        __syncthreads();

        for (int c = 0; c < NCHUNK; c++) {
            if (c + 2 < NCHUNK) {
                PRODUCE(c + 2);
                cpa_wait<1>();   // B(c+1) complete before barrier
            } else {
                cpa_wait<0>();   // tail: all B complete
            }
            __syncthreads();
        }
        #undef PRODUCE
    }
}

// --------------------------------------------------------------------------
extern "C" void kernel_launch(void* const* d_in, const int* in_sizes, int n_in,
                              void* d_out, int out_size) {
    (void)in_sizes; (void)n_in; (void)out_size;
    const float* x    = (const float*)d_in[0];
    const float* coef = (const float*)d_in[1];
    float* out        = (float*)d_out;

    const int smem_bytes = NSTG * STAGE_BYTES;   // 147456
    cudaFuncSetAttribute(cheby_main, cudaFuncAttributeMaxDynamicSharedMemorySize,
                         smem_bytes);

    prep_kernel<<<512, 256>>>(coef);
    tanh_bias_kernel<<<8196, 256>>>(x);
    cheby_main<<<dim3(OUT_F / BN, BATCH / BM), NTHR, smem_bytes>>>(out);
}

// round 10
// speedup vs baseline: 2.3890x; 1.0398x over previous
#include <cuda_runtime.h>
#include <cuda_fp16.h>
#include <cstdint>

// ===========================================================================
// ChebyKANLinear, mma.sync m16n8k16 FP16 (fp32 accumulate).
// R9: tanh fused into producer warps (g_T eliminated), bias via 2MB partials
// (g_Wt0 eliminated). Mainloop identical to R8 (431us, ~71% HMMA pipe).
// ===========================================================================

#define BATCH   8192
#define IN_F    1024
#define OUT_F   1024
#define BM      128
#define BN      256
#define KC      64            // 8 i-values * 8 degrees per chunk
#define NCHUNK  128           // IN_F / 8
#define A_BYTES 16384         // BM * KC * 2 (fp16)
#define B_BYTES 32768         // BN * KC * 2 (fp16)
#define STAGE_BYTES (A_BYTES + B_BYTES)
#define NSTG    3
#define NTHR    384
#define CSCALE  4096.0f
#define OSCALE  (1.0f / 4096.0f)

// Static device scratch (no runtime allocation allowed)
__device__ uint32_t g_BF[(size_t)NCHUNK * 16 * 2048];  // B fp16 frags, 16 MB
__device__ float g_part[512 * OUT_F];                  // bias partials, 2 MB
__device__ float g_bias[OUT_F];

// ---------------------------------------------------------------- utils
__device__ __forceinline__ uint32_t h2pack(float lo, float hi) {
    __half2 h = __floats2half2_rn(lo, hi);
    return *reinterpret_cast<uint32_t*>(&h);
}

__device__ __forceinline__ float fast_tanh(float x) {
    float e = __expf(2.f * x);
    return 1.f - __fdividef(2.f, e + 1.f);
}

__device__ __forceinline__ void cpa16(uint32_t dst, const void* src) {
    asm volatile("cp.async.cg.shared.global [%0], [%1], 16;\n" :: "r"(dst), "l"(src));
}
__device__ __forceinline__ void cpa_commit() { asm volatile("cp.async.commit_group;\n"); }
template <int N>
__device__ __forceinline__ void cpa_wait() {
    asm volatile("cp.async.wait_group %0;\n" :: "n"(N) : "memory");
}

__device__ __forceinline__ void lds128(uint4& v, uint32_t addr) {
    asm volatile("ld.shared.v4.b32 {%0,%1,%2,%3}, [%4];"
                 : "=r"(v.x), "=r"(v.y), "=r"(v.z), "=r"(v.w) : "r"(addr));
}
__device__ __forceinline__ void sts128(uint32_t addr, uint32_t a, uint32_t b,
                                       uint32_t c, uint32_t d) {
    asm volatile("st.shared.v4.b32 [%0], {%1,%2,%3,%4};"
                 :: "r"(addr), "r"(a), "r"(b), "r"(c), "r"(d));
}

__device__ __forceinline__ void mma16(float* c, const uint4& a, uint32_t b0, uint32_t b1) {
    asm volatile(
        "mma.sync.aligned.m16n8k16.row.col.f32.f16.f16.f32 "
        "{%0,%1,%2,%3},{%4,%5,%6,%7},{%8,%9},{%0,%1,%2,%3};\n"
        : "+f"(c[0]), "+f"(c[1]), "+f"(c[2]), "+f"(c[3])
        : "r"(a.x), "r"(a.y), "r"(a.z), "r"(a.w), "r"(b0), "r"(b1));
}

// A-fragment lane swizzle (conflict-free for gen STS.128 and consumer LDS.128)
__device__ __forceinline__ uint32_t a_lswz(uint32_t lane_c) {
    return (lane_c * 16u) ^ (((lane_c >> 3) & 3u) << 4);
}

// ---------------------------------------------------------------- prologues
// B fragments (fp16, scaled by 2^12) + per-block bias partials.
// Block b handles i-pair (i0, i0+1), i0 = (b>>2)*8 + (b&3)*2.
__global__ void __launch_bounds__(256) prep_kernel(const float* __restrict__ coef) {
    __shared__ uint32_t stg[8192];     // [wnG16][nip4][lane32][w4]
    const int b = blockIdx.x;
    const int c = b >> 2, s = b & 3;
    const int i0 = c * 8 + s * 2;
    #pragma unroll
    for (int r = 0; r < 4; r++) {
        const int col = threadIdx.x + (r << 8);
        const float* c0 = coef + (size_t)i0 * 9216 + (size_t)col * 9;
        const float* c1 = c0 + 9216;
        float cv0[9], cv1[9];
        #pragma unroll
        for (int d = 0; d < 9; d++) { cv0[d] = __ldg(c0 + d); cv1[d] = __ldg(c1 + d); }
        const int g = col & 7, colpar = (col >> 3) & 1;
        const int nip = (col >> 4) & 3, wnG = col >> 6;
        const int base = wnG * 512 + nip * 128 + colpar * 2;
        #pragma unroll
        for (int t = 0; t < 4; t++) {
            stg[base + (g * 4 + t) * 4 + 0] =
                h2pack(cv0[2 * t + 1] * CSCALE, cv0[2 * t + 2] * CSCALE);
            stg[base + (g * 4 + t) * 4 + 1] =
                h2pack(cv1[2 * t + 1] * CSCALE, cv1[2 * t + 2] * CSCALE);
        }
        g_part[(size_t)b * OUT_F + col] = cv0[0] + cv1[0];   // bias partial
    }
    __syncthreads();
    // write s-slice: per (c,wnG) block of 512 float4, slice at s*128
    float4* dst = reinterpret_cast<float4*>(g_BF);
    const float4* src = reinterpret_cast<const float4*>(stg);
    #pragma unroll
    for (int k = 0; k < 8; k++) {
        const int q = threadIdx.x + (k << 8);   // 0..2047
        const int wnG = q >> 7, inner = q & 127;
        dst[(size_t)(c * 16 + wnG) * 512 + s * 128 + inner] = src[q];
    }
}

// bias[o] = sum over 512 partials (deterministic fixed order)
__global__ void __launch_bounds__(256) bias_red_kernel() {
    const int o = (blockIdx.x << 8) + threadIdx.x;
    float s0 = 0.f, s1 = 0.f, s2 = 0.f, s3 = 0.f;
    #pragma unroll 4
    for (int b = 0; b < 512; b += 4) {
        s0 += g_part[(size_t)(b + 0) * OUT_F + o];
        s1 += g_part[(size_t)(b + 1) * OUT_F + o];
        s2 += g_part[(size_t)(b + 2) * OUT_F + o];
        s3 += g_part[(size_t)(b + 3) * OUT_F + o];
    }
    g_bias[o] = (s0 + s1) + (s2 + s3);
}

// ---------------------------------------------------------------- main GEMM
// 384 thr: warps 0-7 consumers (128x256 tile, warp 64x64, m16n8k16),
// warps 8-11 producers (tanh fused). 3-stage ring = 144KB.
__global__ void __launch_bounds__(NTHR, 1) cheby_main(const float* __restrict__ X,
                                                      float* __restrict__ Out) {
    extern __shared__ uint8_t sm[];
    const uint32_t smA = (uint32_t)__cvta_generic_to_shared(sm);          // 3 x 16KB
    const uint32_t smB = smA + NSTG * A_BYTES;                            // 3 x 32KB

    const int tid  = threadIdx.x;
    const int lane = tid & 31;
    const int w    = tid >> 5;
    const int bm   = blockIdx.y << 7;
    const int bx   = blockIdx.x;
    const int bn   = bx << 8;

    const float4* bsrc = reinterpret_cast<const float4*>(g_BF);

    if (w < 8) {
        // ======================= CONSUMER (256 threads) =====================
        const int wm = w >> 2;           // 0..1 (64-row block)
        const int wn = w & 3;            // 0..3 (64-col block)
        const int g  = lane >> 2;
        const int t  = lane & 3;
        const uint32_t lsw = a_lswz((uint32_t)lane);

        float acc[4][8][4];
        #pragma unroll
        for (int mi = 0; mi < 4; mi++)
            #pragma unroll
            for (int ni = 0; ni < 8; ni++)
                #pragma unroll
                for (int q = 0; q < 4; q++) acc[mi][ni][q] = 0.f;

        __syncthreads();    // chunks 0,1 produced; B0 complete

        for (int c = 0; c < NCHUNK; c++) {
            const int st = c % NSTG;
            const uint32_t aBase = smA + (uint32_t)(st * A_BYTES + wm * 2048) + lsw;
            const uint32_t bBase = smB + (uint32_t)(st * B_BYTES + wn * 8192 + lane * 16);

            #pragma unroll
            for (int s = 0; s < 4; s++) {
                uint4 aC[4];
                #pragma unroll
                for (int mi = 0; mi < 4; mi++)
                    lds128(aC[mi], aBase + (uint32_t)(s * 4096 + mi * 512));
                uint4 bC[4];
                #pragma unroll
                for (int nip = 0; nip < 4; nip++)
                    lds128(bC[nip], bBase + (uint32_t)(s * 2048 + nip * 512));
                #pragma unroll
                for (int ni = 0; ni < 8; ni++) {
                    const uint32_t b0 = (ni & 1) ? bC[ni >> 1].z : bC[ni >> 1].x;
                    const uint32_t b1 = (ni & 1) ? bC[ni >> 1].w : bC[ni >> 1].y;
                    #pragma unroll
                    for (int mi = 0; mi < 4; mi++)
                        mma16(acc[mi][ni], aC[mi], b0, b1);
                }
            }
            __syncthreads();
        }

        // --- epilogue: out = acc * 2^-12 + bias ---
        #pragma unroll
        for (int ni = 0; ni < 8; ni++) {
            const int cc = bn + (wn << 6) + (ni << 3) + (t << 1);
            const float2 bv = *reinterpret_cast<const float2*>(g_bias + cc);
            #pragma unroll
            for (int mi = 0; mi < 4; mi++) {
                const int r0 = bm + (wm << 6) + (mi << 4) + g;
                float2 o0 = { fmaf(acc[mi][ni][0], OSCALE, bv.x),
                              fmaf(acc[mi][ni][1], OSCALE, bv.y) };
                float2 o1 = { fmaf(acc[mi][ni][2], OSCALE, bv.x),
                              fmaf(acc[mi][ni][3], OSCALE, bv.y) };
                *reinterpret_cast<float2*>(Out + (size_t)r0 * OUT_F + cc)       = o0;
                *reinterpret_cast<float2*>(Out + (size_t)(r0 + 8) * OUT_F + cc) = o1;
            }
        }
    } else {
        // ======================= PRODUCER (128 threads) =====================
        const int ptid = tid - 256;
        // 2 generator units per thread: u = ptid, ptid+128
        // unit u: s = u&3, g = (u>>2)&7, G = u>>5; rows G*16+g, +8; i = 8c+2s,+1

        #define PRODUCE(n)                                                        \
        do {                                                                      \
            const int st_ = (n) % NSTG;                                           \
            /* B: 4 wnG blocks of 512 float4 */                                   \
            const uint32_t dstB_ = smB + (uint32_t)(st_ * B_BYTES);               \
            _Pragma("unroll")                                                     \
            for (int k = 0; k < 16; k++) {                                        \
                const int wng = k >> 2;                                           \
                const int inner = ptid + ((k & 3) << 7);                          \
                cpa16(dstB_ + (uint32_t)(wng * 8192 + inner * 16),                \
                      bsrc + (size_t)((n) * 16 + (bx << 2) + wng) * 512 + inner); \
            }                                                                     \
            cpa_commit();                                                         \
            /* A generation with fused tanh */                                    \
            const uint32_t aDst_ = smA + (uint32_t)(st_ * A_BYTES);               \
            _Pragma("unroll")                                                     \
            for (int e = 0; e < 2; e++) {                                         \
                const int u = ptid + (e << 7);                                    \
                const int s_ = u & 3, g_ = (u >> 2) & 7, G_ = u >> 5;             \
                const int rA = bm + (G_ << 4) + g_;                               \
                const float2 xA = *reinterpret_cast<const float2*>(               \
                    X + (size_t)rA * IN_F + ((n) << 3) + (s_ << 1));              \
                const float2 xB = *reinterpret_cast<const float2*>(               \
                    X + (size_t)(rA + 8) * IN_F + ((n) << 3) + (s_ << 1));        \
                const float tA0 = fast_tanh(xA.x), tA1 = fast_tanh(xA.y);         \
                const float tB0 = fast_tanh(xB.x), tB1 = fast_tanh(xB.y);         \
                float TA0[8], TA1[8], TB0[8], TB1[8];                             \
                TA0[0] = tA0; TA1[0] = tA1; TB0[0] = tB0; TB1[0] = tB1;           \
                TA0[1] = 2.f * tA0 * tA0 - 1.f;                                   \
                TA1[1] = 2.f * tA1 * tA1 - 1.f;                                   \
                TB0[1] = 2.f * tB0 * tB0 - 1.f;                                   \
                TB1[1] = 2.f * tB1 * tB1 - 1.f;                                   \
                _Pragma("unroll")                                                 \
                for (int d = 2; d < 8; d++) {                                     \
                    TA0[d] = 2.f * tA0 * TA0[d - 1] - TA0[d - 2];                 \
                    TA1[d] = 2.f * tA1 * TA1[d - 1] - TA1[d - 2];                 \
                    TB0[d] = 2.f * tB0 * TB0[d - 1] - TB0[d - 2];                 \
                    TB1[d] = 2.f * tB1 * TB1[d - 1] - TB1[d - 2];                 \
                }                                                                 \
                const uint32_t ab_ = aDst_ + (uint32_t)(s_ * 4096 + G_ * 512);    \
                _Pragma("unroll")                                                 \
                for (int t = 0; t < 4; t++)                                       \
                    sts128(ab_ + a_lswz((uint32_t)(g_ * 4 + t)),                  \
                           h2pack(TA0[2 * t], TA0[2 * t + 1]),                    \
                           h2pack(TB0[2 * t], TB0[2 * t + 1]),                    \
                           h2pack(TA1[2 * t], TA1[2 * t + 1]),                    \
                           h2pack(TB1[2 * t], TB1[2 * t + 1]));                   \
            }                                                                     \
        } while (0)

        PRODUCE(0);
        PRODUCE(1);
        cpa_wait<1>();       // B(0) complete
        __syncthreads();

        for (int c = 0; c < NCHUNK; c++) {
            if (c + 2 < NCHUNK) {
                PRODUCE(c + 2);
                cpa_wait<1>();   // B(c+1) complete before barrier
            } else {
                cpa_wait<0>();   // tail: all B complete
            }
            __syncthreads();
        }
        #undef PRODUCE
    }
}

// --------------------------------------------------------------------------
extern "C" void kernel_launch(void* const* d_in, const int* in_sizes, int n_in,
                              void* d_out, int out_size) {
    (void)in_sizes; (void)n_in; (void)out_size;
    const float* x    = (const float*)d_in[0];
    const float* coef = (const float*)d_in[1];
    float* out        = (float*)d_out;

    const int smem_bytes = NSTG * STAGE_BYTES;   // 147456
    cudaFuncSetAttribute(cheby_main, cudaFuncAttributeMaxDynamicSharedMemorySize,
                         smem_bytes);

    prep_kernel<<<512, 256>>>(coef);
    bias_red_kernel<<<4, 256>>>();
    cheby_main<<<dim3(OUT_F / BN, BATCH / BM), NTHR, smem_bytes>>>(x, out);
}